// round 8
// baseline (speedup 1.0000x reference)
#include <cuda_runtime.h>
#include <cuda_bf16.h>
#include <math.h>
#include <stdint.h>

#define BB 8
#define CC 64
#define NN 4096
#define HH 4
#define OO 128
#define KNN 20
#define PP (BB*NN)   // 32768

// ---------------- scratch (device globals; no allocs) ----------------
__device__ float g_cval[(size_t)32*21*PP];    // candidate values [jt*21+k][row] (88 MB)
__device__ int   g_cidx[(size_t)32*21*PP];    // candidate indices (88 MB)
__device__ float g_pts[(size_t)PP*CC];        // (B,N,C) transposed x
__device__ int   g_idx[PP*KNN];
__device__ float g_M[HH*CC*CC];               // Wq^T Wk per head
__device__ float g_tq[(size_t)PP*256];        // q @ M, per point per head
__device__ float g_Wf[OO*HH*CC];              // Wout folded with Wv
__device__ float g_wd[(size_t)PP*HH*CC];      // weighted difference vectors
__device__ float g_y[(size_t)BB*OO*NN];       // pre-BN output
__device__ float g_mean[OO];
__device__ float g_istd[OO];

// ---------------- K: transpose x -> pts (for attn gather / qt) ----------------
__global__ void k_transpose(const float* __restrict__ x) {
    __shared__ float tile[32][33];
    int b = blockIdx.z;
    int n0 = blockIdx.x * 32, c0 = blockIdx.y * 32;
    for (int i = threadIdx.y; i < 32; i += 8)
        tile[i][threadIdx.x] = x[((size_t)b*CC + c0 + i)*NN + n0 + threadIdx.x];
    __syncthreads();
    for (int i = threadIdx.y; i < 32; i += 8)
        g_pts[((size_t)b*NN + n0 + i)*CC + c0 + threadIdx.x] = tile[threadIdx.x][i];
}

// ---------------- K: copy x into out channels [128,192) ----------------
__global__ void k_copyx(const float* __restrict__ x, float* __restrict__ out) {
    size_t i = (size_t)blockIdx.x * blockDim.x + threadIdx.x;
    if (i >= (size_t)BB*CC*NN) return;
    int n = (int)(i & (NN-1));
    size_t t = i >> 12;
    int c = (int)(t & (CC-1));
    int b = (int)(t >> 6);
    out[((size_t)b*192 + 128 + c)*NN + n] = x[i];
}

// ---------------- K: precompute Wf = Wout folded with Wv ----------------
__global__ void k_precWf(const float* __restrict__ Wout, const float* __restrict__ Wv) {
    int id = blockIdx.x * 256 + threadIdx.x;
    int c = id & 63;
    int h = (id >> 6) & 3;
    int o = id >> 8;
    float acc = 0.f;
    #pragma unroll 8
    for (int v = 0; v < 64; v++)
        acc += Wout[o*256 + h*64 + v] * Wv[(h*64 + v)*64 + c];
    g_Wf[id] = acc;
}

// ---------------- K: precompute M = Wq^T Wk per head ----------------
__global__ void k_precM(const float* __restrict__ Wq, const float* __restrict__ Wk) {
    int id = blockIdx.x * 256 + threadIdx.x;
    int cp = id & 63;
    int c  = (id >> 6) & 63;
    int h  = id >> 12;
    float acc = 0.f;
    #pragma unroll 8
    for (int e = 0; e < 64; e++)
        acc += Wq[(h*64 + e)*64 + c] * Wk[(h*64 + e)*64 + cp];
    g_M[id] = acc;
}

// ---------------- K: fused pdist tile + per-tile top-21 candidates ----------------
// smem floats: As [0,8448) 64x132, Bs [8448,16896) 64x132,
//   Ds reuses [0,16768) as 128x131 after MMA,
//   sqa [16896,17024), sqb [17024,17152),
//   lval [17152,19840), lidx [19840,22528)
#define PD_SMEM_BYTES (22528*4)
__global__ void k_pdistk(const float* __restrict__ x) {
    extern __shared__ float sm[];
    float* As  = sm;
    float* Bs  = sm + 8448;
    float* Ds  = sm;                 // reuse after MMA, stride 131
    float* sqa = sm + 16896;
    float* sqb = sm + 17024;
    float* lval = sm + 17152;
    int*   lidx = (int*)(sm + 19840);

    int tid = threadIdx.x;
    int tx = tid & 15, ty = tid >> 4;
    int b = blockIdx.z, it = blockIdx.y, jt = blockIdx.x;
    const float* xb = x + (size_t)b*CC*NN;

    {
        int i0 = it*128, j0 = jt*128;
        #pragma unroll
        for (int w = 0; w < 8; w++) {
            int lin = w*1024 + tid*4;
            int c = lin >> 7, i = lin & 127;
            *(float4*)&As[c*132 + i] = *(const float4*)(xb + (size_t)c*NN + i0 + i);
            *(float4*)&Bs[c*132 + i] = *(const float4*)(xb + (size_t)c*NN + j0 + i);
        }
    }
    __syncthreads();

    if (tid < 128) {
        float s = 0.f;
        #pragma unroll 8
        for (int c = 0; c < 64; c++) { float v = As[c*132 + tid]; s += v*v; }
        sqa[tid] = s;
    } else {
        int t = tid - 128;
        float s = 0.f;
        #pragma unroll 8
        for (int c = 0; c < 64; c++) { float v = Bs[c*132 + t]; s += v*v; }
        sqb[t] = s;
    }
    __syncthreads();

    int aBase = ty*8, bBase = tx*8;

    unsigned long long acc[8][4];
    #pragma unroll
    for (int ii = 0; ii < 8; ii++)
        #pragma unroll
        for (int jp = 0; jp < 4; jp++) acc[ii][jp] = 0ULL;

    #pragma unroll 8
    for (int c = 0; c < 64; c++) {
        float a[8];
        *(float4*)a     = *(float4*)&As[c*132 + aBase];
        *(float4*)(a+4) = *(float4*)&As[c*132 + aBase + 4];
        unsigned long long b2[4];
        #pragma unroll
        for (int jp = 0; jp < 4; jp++)
            b2[jp] = *(const unsigned long long*)&Bs[c*132 + bBase + 2*jp];
        #pragma unroll
        for (int ii = 0; ii < 8; ii++) {
            unsigned long long a2;
            asm("mov.b64 %0, {%1, %1};" : "=l"(a2) : "f"(a[ii]));
            #pragma unroll
            for (int jp = 0; jp < 4; jp++)
                asm("fma.rn.f32x2 %0, %1, %2, %0;" : "+l"(acc[ii][jp]) : "l"(a2), "l"(b2[jp]));
        }
    }

    // read norms into regs, then sync before overwriting As/Bs with D tile
    float sr[8];
    #pragma unroll
    for (int ii = 0; ii < 8; ii++) sr[ii] = sqa[aBase + ii];
    float sj[8];
    #pragma unroll
    for (int j = 0; j < 8; j++) sj[j] = sqb[bBase + j];
    __syncthreads();

    #pragma unroll
    for (int ii = 0; ii < 8; ii++) {
        int r = aBase + ii;
        #pragma unroll
        for (int jp = 0; jp < 4; jp++) {
            unsigned lo, hi;
            asm("mov.b64 {%0, %1}, %2;" : "=r"(lo), "=r"(hi) : "l"(acc[ii][jp]));
            Ds[r*131 + bBase + 2*jp]     = 2.f*__uint_as_float(lo) - sr[ii] - sj[2*jp];
            Ds[r*131 + bBase + 2*jp + 1] = 2.f*__uint_as_float(hi) - sr[ii] - sj[2*jp+1];
        }
    }
    __syncthreads();

    // per-row top-21 over this 128-col tile (threads 0-127)
    if (tid < 128) {
        int LB = tid*21;
        const float* drow = &Ds[tid*131];
        float thr = -3.402823466e38f;
        int cnt = 0;
        #pragma unroll 4
        for (int c = 0; c < 128; c++) {
            float d = drow[c];
            if (d > thr || cnt < 21) {
                int pos = (cnt < 21) ? cnt++ : 20;
                while (pos > 0 && lval[LB + pos - 1] < d) {
                    lval[LB + pos] = lval[LB + pos - 1];
                    lidx[LB + pos] = lidx[LB + pos - 1];
                    pos--;
                }
                lval[LB + pos] = d;
                lidx[LB + pos] = jt*128 + c;
                if (cnt == 21) thr = lval[LB + 20];
            }
        }
        // write candidates, transposed for coalesced merge reads
        int rowg = b*4096 + it*128 + tid;
        #pragma unroll
        for (int k = 0; k < 21; k++) {
            g_cval[(size_t)(jt*21 + k)*PP + rowg] = lval[LB + k];
            g_cidx[(size_t)(jt*21 + k)*PP + rowg] = lidx[LB + k];
        }
    }
}

// ---------------- K: merge 32 sorted slice-lists per row -> top-21 ----------------
__global__ void k_topkmerge() {
    __shared__ float lval[256*21];
    __shared__ int   lidx[256*21];
    int tid = threadIdx.x;
    int r = blockIdx.x*256 + tid;
    int LB = tid*21;

    float thr = -3.402823466e38f;
    int cnt = 0;
    for (int jt = 0; jt < 32; jt++) {
        #pragma unroll 4
        for (int k = 0; k < 21; k++) {
            float d = g_cval[(size_t)(jt*21 + k)*PP + r];
            if (cnt >= 21 && d <= thr) break;   // slice list sorted desc
            int idx = g_cidx[(size_t)(jt*21 + k)*PP + r];
            int pos = (cnt < 21) ? cnt++ : 20;
            while (pos > 0 && lval[LB + pos - 1] < d) {
                lval[LB + pos] = lval[LB + pos - 1];
                lidx[LB + pos] = lidx[LB + pos - 1];
                pos--;
            }
            lval[LB + pos] = d;
            lidx[LB + pos] = idx;
            if (cnt == 21) thr = lval[LB + 20];
        }
    }
    #pragma unroll
    for (int k = 0; k < KNN; k++) g_idx[r*KNN + k] = lidx[LB + 1 + k];
}

// ---------------- K: tq = pts @ M  (all points, all heads) ----------------
__global__ void k_qt() {
    __shared__ float Ms[32][132];
    __shared__ float Qs[64][33];
    int tx = threadIdx.x, ty = threadIdx.y;
    int tid = ty*16 + tx;
    int p0 = blockIdx.x * 64;
    int eb = blockIdx.y * 128;

    float acc[4][8] = {};

    for (int kt = 0; kt < 2; kt++) {
        for (int t = tid; t < 4096; t += 256) {
            int k = t >> 7, o = t & 127;
            int ep = eb + o, h = ep >> 6, e = ep & 63;
            Ms[k][o] = g_M[h*4096 + (kt*32 + k)*64 + e];
        }
        for (int t = tid; t < 2048; t += 256) {
            int pp = t >> 5, k = t & 31;
            Qs[pp][k] = g_pts[(size_t)(p0 + pp)*64 + kt*32 + k];
        }
        __syncthreads();
        #pragma unroll 8
        for (int k = 0; k < 32; k++) {
            float a[4], bb[8];
            #pragma unroll
            for (int pp = 0; pp < 4; pp++) a[pp] = Qs[ty*4 + pp][k];
            *(float4*)bb     = *(float4*)&Ms[k][tx*8];
            *(float4*)(bb+4) = *(float4*)&Ms[k][tx*8 + 4];
            #pragma unroll
            for (int pp = 0; pp < 4; pp++)
                #pragma unroll
                for (int ee = 0; ee < 8; ee++)
                    acc[pp][ee] += a[pp] * bb[ee];
        }
        __syncthreads();
    }
    #pragma unroll
    for (int pp = 0; pp < 4; pp++) {
        size_t rb = (size_t)(p0 + ty*4 + pp)*256 + eb + tx*8;
        *(float4*)&g_tq[rb]     = make_float4(acc[pp][0], acc[pp][1], acc[pp][2], acc[pp][3]);
        *(float4*)&g_tq[rb + 4] = make_float4(acc[pp][4], acc[pp][5], acc[pp][6], acc[pp][7]);
    }
}

// ---------------- K: per-point attention -> weighted difference vectors ----------------
#define WPB 8
__global__ void k_attn() {
    __shared__ float nb[WPB][KNN][65];
    __shared__ float tqs[WPB][64];
    __shared__ float ps[WPB][KNN];
    __shared__ int   nbi[WPB][KNN];

    int w = threadIdx.x >> 5;
    int lane = threadIdx.x & 31;
    int p = blockIdx.x * WPB + w;
    int b = p >> 12;

    if (lane < KNN) nbi[w][lane] = g_idx[p * KNN + lane];
    float q0 = g_pts[(size_t)p*64 + lane];
    float q1 = g_pts[(size_t)p*64 + 32 + lane];
    __syncwarp();
    #pragma unroll 4
    for (int k = 0; k < KNN; k++) {
        int j = nbi[w][k];
        const float* src = g_pts + ((size_t)(b << 12) + j)*64;
        nb[w][k][lane]      = src[lane];
        nb[w][k][lane + 32] = src[lane + 32];
    }
    __syncwarp();

    for (int h = 0; h < HH; h++) {
        tqs[w][lane]      = g_tq[(size_t)p*256 + h*64 + lane];
        tqs[w][lane + 32] = g_tq[(size_t)p*256 + h*64 + 32 + lane];
        __syncwarp();

        float s = -3.402823466e38f;
        if (lane < KNN) {
            float acc = 0.f;
            #pragma unroll 8
            for (int c = 0; c < 64; c++) acc += tqs[w][c] * nb[w][lane][c];
            s = acc * 0.125f;
        }
        float mx = s;
        #pragma unroll
        for (int off = 16; off; off >>= 1) mx = fmaxf(mx, __shfl_xor_sync(0xFFFFFFFFu, mx, off));
        float e = (lane < KNN) ? expf(s - mx) : 0.f;
        float sum = e;
        #pragma unroll
        for (int off = 16; off; off >>= 1) sum += __shfl_xor_sync(0xFFFFFFFFu, sum, off);
        if (lane < KNN) ps[w][lane] = e / sum;
        __syncwarp();

        float w0 = 0.f, w1 = 0.f;
        #pragma unroll 4
        for (int k = 0; k < KNN; k++) {
            float pk = ps[w][k];
            w0 += pk * (nb[w][k][lane]      - q0);
            w1 += pk * (nb[w][k][lane + 32] - q1);
        }
        g_wd[((size_t)p*HH + h)*64 + lane]      = w0;
        g_wd[((size_t)p*HH + h)*64 + 32 + lane] = w1;
        __syncwarp();
    }
}

// ---------------- K: y = Wf (128x256) @ wd^T ----------------
__global__ void k_ygemm() {
    __shared__ float Wfs[32][129];
    __shared__ float wds[64][33];
    int tid = threadIdx.y * 16 + threadIdx.x;
    int p0 = blockIdx.x * 64;
    float acc[8][4] = {};

    for (int kt = 0; kt < 8; kt++) {
        for (int t = tid; t < 4096; t += 256) {
            int o = t >> 5, k = t & 31;
            Wfs[k][o] = g_Wf[o*256 + kt*32 + k];
        }
        for (int t = tid; t < 2048; t += 256) {
            int pp = t >> 5, k = t & 31;
            wds[pp][k] = g_wd[(size_t)(p0 + pp)*256 + kt*32 + k];
        }
        __syncthreads();
        #pragma unroll 8
        for (int k = 0; k < 32; k++) {
            float a[8], bb[4];
            #pragma unroll
            for (int ii = 0; ii < 8; ii++) a[ii] = Wfs[k][threadIdx.y*8 + ii];
            #pragma unroll
            for (int jj = 0; jj < 4; jj++) bb[jj] = wds[threadIdx.x*4 + jj][k];
            #pragma unroll
            for (int ii = 0; ii < 8; ii++)
                #pragma unroll
                for (int jj = 0; jj < 4; jj++)
                    acc[ii][jj] += a[ii] * bb[jj];
        }
        __syncthreads();
    }
    #pragma unroll
    for (int ii = 0; ii < 8; ii++) {
        int o = threadIdx.y*8 + ii;
        #pragma unroll
        for (int jj = 0; jj < 4; jj++) {
            int p = p0 + threadIdx.x*4 + jj;
            g_y[((size_t)(p >> 12)*OO + o)*NN + (p & 4095)] = acc[ii][jj];
        }
    }
}

// ---------------- K: BN stats (double accumulation) ----------------
__global__ void k_bnstats() {
    __shared__ double rs[256], rss[256];
    int o = blockIdx.x;
    int tid = threadIdx.x;
    double s = 0.0, ss = 0.0;
    for (int b = 0; b < BB; b++) {
        const float* row = g_y + ((size_t)b*OO + o)*NN;
        for (int t = tid; t < NN; t += 256) {
            double v = (double)row[t];
            s += v; ss += v*v;
        }
    }
    rs[tid] = s; rss[tid] = ss;
    __syncthreads();
    for (int st = 128; st; st >>= 1) {
        if (tid < st) { rs[tid] += rs[tid + st]; rss[tid] += rss[tid + st]; }
        __syncthreads();
    }
    if (tid == 0) {
        double n = (double)(BB*NN);
        double mean = rs[0] / n;
        double var = rss[0] / n - mean*mean;
        g_mean[o] = (float)mean;
        g_istd[o] = (float)(1.0 / sqrt(var + 1e-5));
    }
}

// ---------------- K: BN apply + LeakyReLU -> out channels [0,128) ----------------
__global__ void k_bnapply(const float* __restrict__ gamma, const float* __restrict__ beta,
                          float* __restrict__ out) {
    size_t i = (size_t)blockIdx.x * blockDim.x + threadIdx.x;
    if (i >= (size_t)BB*OO*NN) return;
    int n = (int)(i & (NN-1));
    size_t t = i >> 12;
    int o = (int)(t & (OO-1));
    int b = (int)(t >> 7);
    float v = (g_y[i] - g_mean[o]) * g_istd[o] * gamma[o] + beta[o];
    v = (v >= 0.f) ? v : 0.2f * v;
    out[((size_t)b*192 + o)*NN + n] = v;
}

// ---------------- launch ----------------
extern "C" void kernel_launch(void* const* d_in, const int* in_sizes, int n_in,
                              void* d_out, int out_size) {
    const float* x     = (const float*)d_in[0];
    const float* Wq    = (const float*)d_in[1];
    const float* Wk    = (const float*)d_in[2];
    const float* Wv    = (const float*)d_in[3];
    const float* Wout  = (const float*)d_in[4];
    const float* gamma = (const float*)d_in[5];
    const float* beta  = (const float*)d_in[6];
    float* out = (float*)d_out;

    cudaFuncSetAttribute(k_pdistk, cudaFuncAttributeMaxDynamicSharedMemorySize, PD_SMEM_BYTES);

    k_transpose<<<dim3(NN/32, CC/32, BB), dim3(32, 8)>>>(x);
    k_precWf<<<128, 256>>>(Wout, Wv);
    k_precM<<<64, 256>>>(Wq, Wk);
    k_pdistk<<<dim3(32, 32, BB), 256, PD_SMEM_BYTES>>>(x);   // 4th launch -> profiled
    k_topkmerge<<<PP/256, 256>>>();
    k_copyx<<<(BB*CC*NN)/256, 256>>>(x, out);
    k_qt<<<dim3(PP/64, 2), dim3(16, 16)>>>();
    k_attn<<<PP/WPB, 256>>>();
    k_ygemm<<<PP/64, dim3(16, 16)>>>();
    k_bnstats<<<OO, 256>>>();
    k_bnapply<<<(BB*OO*NN)/256, 256>>>(gamma, beta, out);
}

// round 9
// speedup vs baseline: 3.4895x; 3.4895x over previous
#include <cuda_runtime.h>
#include <cuda_bf16.h>
#include <math.h>
#include <stdint.h>

#define BB 8
#define CC 64
#define NN 4096
#define HH 4
#define OO 128
#define KNN 20
#define PP (BB*NN)   // 32768

// ---------------- scratch (device globals; no allocs) ----------------
__device__ float g_pdist[(size_t)BB*NN*NN];   // 536 MB
__device__ float g_pts[(size_t)PP*CC];        // (B,N,C) transposed x
__device__ int   g_idx[PP*KNN];
__device__ float g_M[HH*CC*CC];               // Wq^T Wk per head
__device__ float g_tq[(size_t)PP*256];        // q @ M, per point per head
__device__ float g_Wf[OO*HH*CC];              // Wout folded with Wv
__device__ float g_wd[(size_t)PP*HH*CC];      // weighted difference vectors
__device__ float g_y[(size_t)BB*OO*NN];       // pre-BN output
__device__ float g_mean[OO];
__device__ float g_istd[OO];

// ---------------- K: transpose x -> pts (for attn gather / qt) ----------------
__global__ void k_transpose(const float* __restrict__ x) {
    __shared__ float tile[32][33];
    int b = blockIdx.z;
    int n0 = blockIdx.x * 32, c0 = blockIdx.y * 32;
    for (int i = threadIdx.y; i < 32; i += 8)
        tile[i][threadIdx.x] = x[((size_t)b*CC + c0 + i)*NN + n0 + threadIdx.x];
    __syncthreads();
    for (int i = threadIdx.y; i < 32; i += 8)
        g_pts[((size_t)b*NN + n0 + i)*CC + c0 + threadIdx.x] = tile[threadIdx.x][i];
}

// ---------------- K: copy x into out channels [128,192) ----------------
__global__ void k_copyx(const float* __restrict__ x, float* __restrict__ out) {
    size_t i = (size_t)blockIdx.x * blockDim.x + threadIdx.x;
    if (i >= (size_t)BB*CC*NN) return;
    int n = (int)(i & (NN-1));
    size_t t = i >> 12;
    int c = (int)(t & (CC-1));
    int b = (int)(t >> 6);
    out[((size_t)b*192 + 128 + c)*NN + n] = x[i];
}

// ---------------- K: precompute Wf = Wout folded with Wv ----------------
__global__ void k_precWf(const float* __restrict__ Wout, const float* __restrict__ Wv) {
    int id = blockIdx.x * 256 + threadIdx.x;
    int c = id & 63;
    int h = (id >> 6) & 3;
    int o = id >> 8;
    float acc = 0.f;
    #pragma unroll 8
    for (int v = 0; v < 64; v++)
        acc += Wout[o*256 + h*64 + v] * Wv[(h*64 + v)*64 + c];
    g_Wf[id] = acc;
}

// ---------------- K: precompute M = Wq^T Wk per head ----------------
__global__ void k_precM(const float* __restrict__ Wq, const float* __restrict__ Wk) {
    int id = blockIdx.x * 256 + threadIdx.x;
    int cp = id & 63;
    int c  = (id >> 6) & 63;
    int h  = id >> 12;
    float acc = 0.f;
    #pragma unroll 8
    for (int e = 0; e < 64; e++)
        acc += Wq[(h*64 + e)*64 + c] * Wk[(h*64 + e)*64 + cp];
    g_M[id] = acc;
}

// ---------------- K: pdist = 2*dot - si - sj  (f32x2 packed, 128x128 tiles) ----------------
#define PD_SMEM_BYTES (17152*4)
__global__ void k_pdist(const float* __restrict__ x) {
    extern __shared__ float sm[];
    float* As  = sm;
    float* Bs  = sm + 8448;
    float* sqa = sm + 16896;
    float* sqb = sm + 17024;

    int tid = threadIdx.x;
    int tx = tid & 15, ty = tid >> 4;
    int b = blockIdx.z, it = blockIdx.y, jt = blockIdx.x;
    const float* xb = x + (size_t)b*CC*NN;

    {
        int i0 = it*128, j0 = jt*128;
        #pragma unroll
        for (int w = 0; w < 8; w++) {
            int lin = w*1024 + tid*4;
            int c = lin >> 7, i = lin & 127;
            *(float4*)&As[c*132 + i] = *(const float4*)(xb + (size_t)c*NN + i0 + i);
            *(float4*)&Bs[c*132 + i] = *(const float4*)(xb + (size_t)c*NN + j0 + i);
        }
    }
    __syncthreads();

    if (tid < 128) {
        float s = 0.f;
        #pragma unroll 8
        for (int c = 0; c < 64; c++) { float v = As[c*132 + tid]; s += v*v; }
        sqa[tid] = s;
    } else {
        int t = tid - 128;
        float s = 0.f;
        #pragma unroll 8
        for (int c = 0; c < 64; c++) { float v = Bs[c*132 + t]; s += v*v; }
        sqb[t] = s;
    }
    __syncthreads();

    int aBase = ty*8, bBase = tx*8;

    unsigned long long acc[8][4];
    #pragma unroll
    for (int ii = 0; ii < 8; ii++)
        #pragma unroll
        for (int jp = 0; jp < 4; jp++) acc[ii][jp] = 0ULL;

    #pragma unroll 8
    for (int c = 0; c < 64; c++) {
        float a[8];
        *(float4*)a     = *(float4*)&As[c*132 + aBase];
        *(float4*)(a+4) = *(float4*)&As[c*132 + aBase + 4];
        unsigned long long b2[4];
        #pragma unroll
        for (int jp = 0; jp < 4; jp++)
            b2[jp] = *(const unsigned long long*)&Bs[c*132 + bBase + 2*jp];
        #pragma unroll
        for (int ii = 0; ii < 8; ii++) {
            unsigned long long a2;
            asm("mov.b64 %0, {%1, %1};" : "=l"(a2) : "f"(a[ii]));
            #pragma unroll
            for (int jp = 0; jp < 4; jp++)
                asm("fma.rn.f32x2 %0, %1, %2, %0;" : "+l"(acc[ii][jp]) : "l"(a2), "l"(b2[jp]));
        }
    }

    #pragma unroll
    for (int ii = 0; ii < 8; ii++) {
        int r = aBase + ii;
        float sr = sqa[r];
        float o[8];
        #pragma unroll
        for (int jp = 0; jp < 4; jp++) {
            unsigned lo, hi;
            asm("mov.b64 {%0, %1}, %2;" : "=r"(lo), "=r"(hi) : "l"(acc[ii][jp]));
            o[2*jp]   = 2.f*__uint_as_float(lo) - sr - sqb[bBase + 2*jp];
            o[2*jp+1] = 2.f*__uint_as_float(hi) - sr - sqb[bBase + 2*jp + 1];
        }
        size_t g = ((size_t)(b*4096 + it*128 + r))*4096 + jt*128 + bBase;
        *(float4*)&g_pdist[g]     = make_float4(o[0], o[1], o[2], o[3]);
        *(float4*)&g_pdist[g + 4] = make_float4(o[4], o[5], o[6], o[7]);
    }
}

// ---------------- K: top-21 per row, two-level incremental argmax ----------------
// One block (128 threads) per row. Row loaded contiguously (DRAM-friendly).
// Each thread owns a 32-element strided strip (cols = i*128 + tid) and keeps its
// strip max in registers. 21 iterations of block-argmax with exact
// (value desc, index asc) tie ordering; only the winner rescans its strip.
__global__ void k_topk2() {
    __shared__ float srow[4096];
    __shared__ float swv[4];
    __shared__ int   swi[4];
    __shared__ int   s_bwi;
    __shared__ int   outIdx[KNN + 1];

    int tid = threadIdx.x;
    int lane = tid & 31, wid = tid >> 5;
    size_t base = (size_t)blockIdx.x * 4096;

    // load row (coalesced, contiguous) + strip max
    float mv = -3.402823466e38f;
    int midx = 0;
    #pragma unroll 8
    for (int i = 0; i < 32; i++) {
        float d = g_pdist[base + i*128 + tid];
        srow[i*128 + tid] = d;
        if (d > mv) { mv = d; midx = i*128 + tid; }   // ascending idx, strict > => smallest-index tie win
    }

    for (int sel = 0; sel < KNN + 1; sel++) {
        // warp argmax (val desc, idx asc)
        float rv = mv; int ri = midx;
        #pragma unroll
        for (int off = 16; off; off >>= 1) {
            float ov = __shfl_xor_sync(0xFFFFFFFFu, rv, off);
            int   oi = __shfl_xor_sync(0xFFFFFFFFu, ri, off);
            if (ov > rv || (ov == rv && oi < ri)) { rv = ov; ri = oi; }
        }
        if (lane == 0) { swv[wid] = rv; swi[wid] = ri; }
        __syncthreads();
        if (tid == 0) {
            float bv = swv[0]; int bi = swi[0];
            #pragma unroll
            for (int w = 1; w < 4; w++)
                if (swv[w] > bv || (swv[w] == bv && swi[w] < bi)) { bv = swv[w]; bi = swi[w]; }
            s_bwi = bi;
            outIdx[sel] = bi;
        }
        __syncthreads();
        int bi = s_bwi;
        if ((bi & 127) == tid) {
            // owner: mark and rescan strip
            srow[bi] = -3.402823466e38f;
            mv = -3.402823466e38f; midx = tid;
            #pragma unroll 8
            for (int i = 0; i < 32; i++) {
                float d = srow[i*128 + tid];
                if (d > mv) { mv = d; midx = i*128 + tid; }
            }
        }
    }

    if (tid < KNN) g_idx[blockIdx.x * KNN + tid] = outIdx[tid + 1];
}

// ---------------- K: tq = pts @ M  (all points, all heads) ----------------
__global__ void k_qt() {
    __shared__ float Ms[32][132];
    __shared__ float Qs[64][33];
    int tx = threadIdx.x, ty = threadIdx.y;
    int tid = ty*16 + tx;
    int p0 = blockIdx.x * 64;
    int eb = blockIdx.y * 128;

    float acc[4][8] = {};

    for (int kt = 0; kt < 2; kt++) {
        for (int t = tid; t < 4096; t += 256) {
            int k = t >> 7, o = t & 127;
            int ep = eb + o, h = ep >> 6, e = ep & 63;
            Ms[k][o] = g_M[h*4096 + (kt*32 + k)*64 + e];
        }
        for (int t = tid; t < 2048; t += 256) {
            int pp = t >> 5, k = t & 31;
            Qs[pp][k] = g_pts[(size_t)(p0 + pp)*64 + kt*32 + k];
        }
        __syncthreads();
        #pragma unroll 8
        for (int k = 0; k < 32; k++) {
            float a[4], bb[8];
            #pragma unroll
            for (int pp = 0; pp < 4; pp++) a[pp] = Qs[ty*4 + pp][k];
            *(float4*)bb     = *(float4*)&Ms[k][tx*8];
            *(float4*)(bb+4) = *(float4*)&Ms[k][tx*8 + 4];
            #pragma unroll
            for (int pp = 0; pp < 4; pp++)
                #pragma unroll
                for (int ee = 0; ee < 8; ee++)
                    acc[pp][ee] += a[pp] * bb[ee];
        }
        __syncthreads();
    }
    #pragma unroll
    for (int pp = 0; pp < 4; pp++) {
        size_t rb = (size_t)(p0 + ty*4 + pp)*256 + eb + tx*8;
        *(float4*)&g_tq[rb]     = make_float4(acc[pp][0], acc[pp][1], acc[pp][2], acc[pp][3]);
        *(float4*)&g_tq[rb + 4] = make_float4(acc[pp][4], acc[pp][5], acc[pp][6], acc[pp][7]);
    }
}

// ---------------- K: per-point attention -> weighted difference vectors ----------------
#define WPB 8
__global__ void k_attn() {
    __shared__ float nb[WPB][KNN][65];
    __shared__ float tqs[WPB][64];
    __shared__ float ps[WPB][KNN];
    __shared__ int   nbi[WPB][KNN];

    int w = threadIdx.x >> 5;
    int lane = threadIdx.x & 31;
    int p = blockIdx.x * WPB + w;
    int b = p >> 12;

    if (lane < KNN) nbi[w][lane] = g_idx[p * KNN + lane];
    float q0 = g_pts[(size_t)p*64 + lane];
    float q1 = g_pts[(size_t)p*64 + 32 + lane];
    __syncwarp();
    #pragma unroll 4
    for (int k = 0; k < KNN; k++) {
        int j = nbi[w][k];
        const float* src = g_pts + ((size_t)(b << 12) + j)*64;
        nb[w][k][lane]      = src[lane];
        nb[w][k][lane + 32] = src[lane + 32];
    }
    __syncwarp();

    for (int h = 0; h < HH; h++) {
        tqs[w][lane]      = g_tq[(size_t)p*256 + h*64 + lane];
        tqs[w][lane + 32] = g_tq[(size_t)p*256 + h*64 + 32 + lane];
        __syncwarp();

        float s = -3.402823466e38f;
        if (lane < KNN) {
            float acc = 0.f;
            #pragma unroll 8
            for (int c = 0; c < 64; c++) acc += tqs[w][c] * nb[w][lane][c];
            s = acc * 0.125f;
        }
        float mx = s;
        #pragma unroll
        for (int off = 16; off; off >>= 1) mx = fmaxf(mx, __shfl_xor_sync(0xFFFFFFFFu, mx, off));
        float e = (lane < KNN) ? expf(s - mx) : 0.f;
        float sum = e;
        #pragma unroll
        for (int off = 16; off; off >>= 1) sum += __shfl_xor_sync(0xFFFFFFFFu, sum, off);
        if (lane < KNN) ps[w][lane] = e / sum;
        __syncwarp();

        float w0 = 0.f, w1 = 0.f;
        #pragma unroll 4
        for (int k = 0; k < KNN; k++) {
            float pk = ps[w][k];
            w0 += pk * (nb[w][k][lane]      - q0);
            w1 += pk * (nb[w][k][lane + 32] - q1);
        }
        g_wd[((size_t)p*HH + h)*64 + lane]      = w0;
        g_wd[((size_t)p*HH + h)*64 + 32 + lane] = w1;
        __syncwarp();
    }
}

// ---------------- K: y = Wf (128x256) @ wd^T ----------------
__global__ void k_ygemm() {
    __shared__ float Wfs[32][129];
    __shared__ float wds[64][33];
    int tid = threadIdx.y * 16 + threadIdx.x;
    int p0 = blockIdx.x * 64;
    float acc[8][4] = {};

    for (int kt = 0; kt < 8; kt++) {
        for (int t = tid; t < 4096; t += 256) {
            int o = t >> 5, k = t & 31;
            Wfs[k][o] = g_Wf[o*256 + kt*32 + k];
        }
        for (int t = tid; t < 2048; t += 256) {
            int pp = t >> 5, k = t & 31;
            wds[pp][k] = g_wd[(size_t)(p0 + pp)*256 + kt*32 + k];
        }
        __syncthreads();
        #pragma unroll 8
        for (int k = 0; k < 32; k++) {
            float a[8], bb[4];
            #pragma unroll
            for (int ii = 0; ii < 8; ii++) a[ii] = Wfs[k][threadIdx.y*8 + ii];
            #pragma unroll
            for (int jj = 0; jj < 4; jj++) bb[jj] = wds[threadIdx.x*4 + jj][k];
            #pragma unroll
            for (int ii = 0; ii < 8; ii++)
                #pragma unroll
                for (int jj = 0; jj < 4; jj++)
                    acc[ii][jj] += a[ii] * bb[jj];
        }
        __syncthreads();
    }
    #pragma unroll
    for (int ii = 0; ii < 8; ii++) {
        int o = threadIdx.y*8 + ii;
        #pragma unroll
        for (int jj = 0; jj < 4; jj++) {
            int p = p0 + threadIdx.x*4 + jj;
            g_y[((size_t)(p >> 12)*OO + o)*NN + (p & 4095)] = acc[ii][jj];
        }
    }
}

// ---------------- K: BN stats (double accumulation) ----------------
__global__ void k_bnstats() {
    __shared__ double rs[256], rss[256];
    int o = blockIdx.x;
    int tid = threadIdx.x;
    double s = 0.0, ss = 0.0;
    for (int b = 0; b < BB; b++) {
        const float* row = g_y + ((size_t)b*OO + o)*NN;
        for (int t = tid; t < NN; t += 256) {
            double v = (double)row[t];
            s += v; ss += v*v;
        }
    }
    rs[tid] = s; rss[tid] = ss;
    __syncthreads();
    for (int st = 128; st; st >>= 1) {
        if (tid < st) { rs[tid] += rs[tid + st]; rss[tid] += rss[tid + st]; }
        __syncthreads();
    }
    if (tid == 0) {
        double n = (double)(BB*NN);
        double mean = rs[0] / n;
        double var = rss[0] / n - mean*mean;
        g_mean[o] = (float)mean;
        g_istd[o] = (float)(1.0 / sqrt(var + 1e-5));
    }
}

// ---------------- K: BN apply + LeakyReLU -> out channels [0,128) ----------------
__global__ void k_bnapply(const float* __restrict__ gamma, const float* __restrict__ beta,
                          float* __restrict__ out) {
    size_t i = (size_t)blockIdx.x * blockDim.x + threadIdx.x;
    if (i >= (size_t)BB*OO*NN) return;
    int n = (int)(i & (NN-1));
    size_t t = i >> 12;
    int o = (int)(t & (OO-1));
    int b = (int)(t >> 7);
    float v = (g_y[i] - g_mean[o]) * g_istd[o] * gamma[o] + beta[o];
    v = (v >= 0.f) ? v : 0.2f * v;
    out[((size_t)b*192 + o)*NN + n] = v;
}

// ---------------- launch ----------------
extern "C" void kernel_launch(void* const* d_in, const int* in_sizes, int n_in,
                              void* d_out, int out_size) {
    const float* x     = (const float*)d_in[0];
    const float* Wq    = (const float*)d_in[1];
    const float* Wk    = (const float*)d_in[2];
    const float* Wv    = (const float*)d_in[3];
    const float* Wout  = (const float*)d_in[4];
    const float* gamma = (const float*)d_in[5];
    const float* beta  = (const float*)d_in[6];
    float* out = (float*)d_out;

    cudaFuncSetAttribute(k_pdist, cudaFuncAttributeMaxDynamicSharedMemorySize, PD_SMEM_BYTES);

    k_transpose<<<dim3(NN/32, CC/32, BB), dim3(32, 8)>>>(x);
    k_precWf<<<128, 256>>>(Wout, Wv);
    k_pdist<<<dim3(32, 32, BB), 256, PD_SMEM_BYTES>>>(x);
    k_topk2<<<PP, 128>>>();                                  // 4th launch -> profiled
    k_precM<<<64, 256>>>(Wq, Wk);
    k_copyx<<<(BB*CC*NN)/256, 256>>>(x, out);
    k_qt<<<dim3(PP/64, 2), dim3(16, 16)>>>();
    k_attn<<<PP/WPB, 256>>>();
    k_ygemm<<<PP/64, dim3(16, 16)>>>();
    k_bnstats<<<OO, 256>>>();
    k_bnapply<<<(BB*OO*NN)/256, 256>>>(gamma, beta, out);
}

// round 10
// speedup vs baseline: 3.4962x; 1.0019x over previous
#include <cuda_runtime.h>
#include <cuda_bf16.h>
#include <math.h>
#include <stdint.h>

#define BB 8
#define CC 64
#define NN 4096
#define HH 4
#define OO 128
#define KNN 20
#define PP (BB*NN)   // 32768

// ---------------- scratch (device globals; no allocs) ----------------
__device__ float g_pdist[(size_t)BB*NN*NN];   // 536 MB
__device__ float g_pts[(size_t)PP*CC];        // (B,N,C) transposed x
__device__ int   g_idx[PP*KNN];
__device__ float g_M[HH*CC*CC];               // Wq^T Wk per head
__device__ float g_tq[(size_t)PP*256];        // q @ M, per point per head
__device__ float g_Wf[OO*HH*CC];              // Wout folded with Wv
__device__ float g_wd[(size_t)PP*HH*CC];      // weighted difference vectors
__device__ float g_y[(size_t)BB*OO*NN];       // pre-BN output
__device__ float g_mean[OO];
__device__ float g_istd[OO];

// ---------------- K: transpose x -> pts (for attn gather / qt) ----------------
__global__ void k_transpose(const float* __restrict__ x) {
    __shared__ float tile[32][33];
    int b = blockIdx.z;
    int n0 = blockIdx.x * 32, c0 = blockIdx.y * 32;
    for (int i = threadIdx.y; i < 32; i += 8)
        tile[i][threadIdx.x] = x[((size_t)b*CC + c0 + i)*NN + n0 + threadIdx.x];
    __syncthreads();
    for (int i = threadIdx.y; i < 32; i += 8)
        g_pts[((size_t)b*NN + n0 + i)*CC + c0 + threadIdx.x] = tile[threadIdx.x][i];
}

// ---------------- K: copy x into out channels [128,192) ----------------
__global__ void k_copyx(const float* __restrict__ x, float* __restrict__ out) {
    size_t i = (size_t)blockIdx.x * blockDim.x + threadIdx.x;
    if (i >= (size_t)BB*CC*NN) return;
    int n = (int)(i & (NN-1));
    size_t t = i >> 12;
    int c = (int)(t & (CC-1));
    int b = (int)(t >> 6);
    out[((size_t)b*192 + 128 + c)*NN + n] = x[i];
}

// ---------------- K: precompute Wf = Wout folded with Wv ----------------
__global__ void k_precWf(const float* __restrict__ Wout, const float* __restrict__ Wv) {
    int id = blockIdx.x * 256 + threadIdx.x;
    int c = id & 63;
    int h = (id >> 6) & 3;
    int o = id >> 8;
    float acc = 0.f;
    #pragma unroll 8
    for (int v = 0; v < 64; v++)
        acc += Wout[o*256 + h*64 + v] * Wv[(h*64 + v)*64 + c];
    g_Wf[id] = acc;
}

// ---------------- K: precompute M = Wq^T Wk per head ----------------
__global__ void k_precM(const float* __restrict__ Wq, const float* __restrict__ Wk) {
    int id = blockIdx.x * 256 + threadIdx.x;
    int cp = id & 63;
    int c  = (id >> 6) & 63;
    int h  = id >> 12;
    float acc = 0.f;
    #pragma unroll 8
    for (int e = 0; e < 64; e++)
        acc += Wq[(h*64 + e)*64 + c] * Wk[(h*64 + e)*64 + cp];
    g_M[id] = acc;
}

// ---------------- K: pdist = 2*dot - si - sj  (f32x2 packed, 128x128 tiles) ----------------
#define PD_SMEM_BYTES (17152*4)
__global__ void k_pdist(const float* __restrict__ x) {
    extern __shared__ float sm[];
    float* As  = sm;
    float* Bs  = sm + 8448;
    float* sqa = sm + 16896;
    float* sqb = sm + 17024;

    int tid = threadIdx.x;
    int tx = tid & 15, ty = tid >> 4;
    int b = blockIdx.z, it = blockIdx.y, jt = blockIdx.x;
    const float* xb = x + (size_t)b*CC*NN;

    {
        int i0 = it*128, j0 = jt*128;
        #pragma unroll
        for (int w = 0; w < 8; w++) {
            int lin = w*1024 + tid*4;
            int c = lin >> 7, i = lin & 127;
            *(float4*)&As[c*132 + i] = *(const float4*)(xb + (size_t)c*NN + i0 + i);
            *(float4*)&Bs[c*132 + i] = *(const float4*)(xb + (size_t)c*NN + j0 + i);
        }
    }
    __syncthreads();

    if (tid < 128) {
        float s = 0.f;
        #pragma unroll 8
        for (int c = 0; c < 64; c++) { float v = As[c*132 + tid]; s += v*v; }
        sqa[tid] = s;
    } else {
        int t = tid - 128;
        float s = 0.f;
        #pragma unroll 8
        for (int c = 0; c < 64; c++) { float v = Bs[c*132 + t]; s += v*v; }
        sqb[t] = s;
    }
    __syncthreads();

    int aBase = ty*8, bBase = tx*8;

    unsigned long long acc[8][4];
    #pragma unroll
    for (int ii = 0; ii < 8; ii++)
        #pragma unroll
        for (int jp = 0; jp < 4; jp++) acc[ii][jp] = 0ULL;

    #pragma unroll 8
    for (int c = 0; c < 64; c++) {
        float a[8];
        *(float4*)a     = *(float4*)&As[c*132 + aBase];
        *(float4*)(a+4) = *(float4*)&As[c*132 + aBase + 4];
        unsigned long long b2[4];
        #pragma unroll
        for (int jp = 0; jp < 4; jp++)
            b2[jp] = *(const unsigned long long*)&Bs[c*132 + bBase + 2*jp];
        #pragma unroll
        for (int ii = 0; ii < 8; ii++) {
            unsigned long long a2;
            asm("mov.b64 %0, {%1, %1};" : "=l"(a2) : "f"(a[ii]));
            #pragma unroll
            for (int jp = 0; jp < 4; jp++)
                asm("fma.rn.f32x2 %0, %1, %2, %0;" : "+l"(acc[ii][jp]) : "l"(a2), "l"(b2[jp]));
        }
    }

    #pragma unroll
    for (int ii = 0; ii < 8; ii++) {
        int r = aBase + ii;
        float sr = sqa[r];
        float o[8];
        #pragma unroll
        for (int jp = 0; jp < 4; jp++) {
            unsigned lo, hi;
            asm("mov.b64 {%0, %1}, %2;" : "=r"(lo), "=r"(hi) : "l"(acc[ii][jp]));
            o[2*jp]   = 2.f*__uint_as_float(lo) - sr - sqb[bBase + 2*jp];
            o[2*jp+1] = 2.f*__uint_as_float(hi) - sr - sqb[bBase + 2*jp + 1];
        }
        size_t g = ((size_t)(b*4096 + it*128 + r))*4096 + jt*128 + bBase;
        *(float4*)&g_pdist[g]     = make_float4(o[0], o[1], o[2], o[3]);
        *(float4*)&g_pdist[g + 4] = make_float4(o[4], o[5], o[6], o[7]);
    }
}

// ---------------- K: top-20 per row, warp-independent REDUX extraction ----------------
// One block (128 thr = 4 warps) per row. Warp w owns cols [w*1024,(w+1)*1024);
// lane owns 32 strided cols. Keys are order-preserving u32 (self -> 0).
// 20 REDUX-argmax extractions per warp (no block barriers), then rank-merge of
// the 80 candidates. Exact (value desc, col asc) tie semantics throughout.
__global__ void k_topk3() {
    __shared__ unsigned usrow[4096];
    __shared__ unsigned cand_u[80];
    __shared__ int      cand_c[80];

    int tid = threadIdx.x;
    int lane = tid & 31, w = tid >> 5;
    size_t base = (size_t)blockIdx.x * 4096;
    int selfcol = blockIdx.x & 4095;

    // load + transform to ordered u32; track per-lane strip max (smallest col on tie)
    unsigned mv = 0u; unsigned mi = 0xFFFFFFFFu;
    int cbase = w*1024 + lane;
    #pragma unroll 8
    for (int i = 0; i < 32; i++) {
        int col = cbase + i*32;
        float f = g_pdist[base + col];
        unsigned u = __float_as_uint(f);
        u = (u & 0x80000000u) ? ~u : (u | 0x80000000u);
        if (col == selfcol) u = 0u;
        usrow[col] = u;
        if (u > mv) { mv = u; mi = (unsigned)col; }
    }
    __syncwarp();

    for (int it = 0; it < KNN; it++) {
        unsigned m  = __reduce_max_sync(0xFFFFFFFFu, mv);
        unsigned mc = __reduce_min_sync(0xFFFFFFFFu, (mv == m) ? mi : 0xFFFFFFFFu);
        if (lane == 0) { cand_u[w*KNN + it] = m; cand_c[w*KNN + it] = (int)mc; }
        int owner = (int)(mc & 31u);
        if (lane == owner) usrow[mc] = 0u;
        __syncwarp();
        // cooperative rescan of owner's strip: element i=lane at col w*1024+lane*32+owner
        int col2 = w*1024 + lane*32 + owner;
        unsigned q  = usrow[col2];
        unsigned m2 = __reduce_max_sync(0xFFFFFFFFu, q);
        unsigned c2 = __reduce_min_sync(0xFFFFFFFFu, (q == m2) ? (unsigned)col2 : 0xFFFFFFFFu);
        if (lane == owner) { mv = m2; mi = c2; }
        __syncwarp();
    }
    __syncthreads();

    // rank-merge 80 candidates -> top-20 set (rank gives unique slots)
    if (tid < 80) {
        unsigned u = cand_u[tid]; int c = cand_c[tid];
        int rank = 0;
        #pragma unroll 8
        for (int j = 0; j < 80; j++) {
            unsigned uj = cand_u[j]; int cj = cand_c[j];
            rank += (uj > u || (uj == u && cj < c)) ? 1 : 0;
        }
        if (rank < KNN) g_idx[blockIdx.x * KNN + rank] = c;
    }
}

// ---------------- K: tq = pts @ M  (all points, all heads) ----------------
__global__ void k_qt() {
    __shared__ float Ms[32][132];
    __shared__ float Qs[64][33];
    int tx = threadIdx.x, ty = threadIdx.y;
    int tid = ty*16 + tx;
    int p0 = blockIdx.x * 64;
    int eb = blockIdx.y * 128;

    float acc[4][8] = {};

    for (int kt = 0; kt < 2; kt++) {
        for (int t = tid; t < 4096; t += 256) {
            int k = t >> 7, o = t & 127;
            int ep = eb + o, h = ep >> 6, e = ep & 63;
            Ms[k][o] = g_M[h*4096 + (kt*32 + k)*64 + e];
        }
        for (int t = tid; t < 2048; t += 256) {
            int pp = t >> 5, k = t & 31;
            Qs[pp][k] = g_pts[(size_t)(p0 + pp)*64 + kt*32 + k];
        }
        __syncthreads();
        #pragma unroll 8
        for (int k = 0; k < 32; k++) {
            float a[4], bb[8];
            #pragma unroll
            for (int pp = 0; pp < 4; pp++) a[pp] = Qs[ty*4 + pp][k];
            *(float4*)bb     = *(float4*)&Ms[k][tx*8];
            *(float4*)(bb+4) = *(float4*)&Ms[k][tx*8 + 4];
            #pragma unroll
            for (int pp = 0; pp < 4; pp++)
                #pragma unroll
                for (int ee = 0; ee < 8; ee++)
                    acc[pp][ee] += a[pp] * bb[ee];
        }
        __syncthreads();
    }
    #pragma unroll
    for (int pp = 0; pp < 4; pp++) {
        size_t rb = (size_t)(p0 + ty*4 + pp)*256 + eb + tx*8;
        *(float4*)&g_tq[rb]     = make_float4(acc[pp][0], acc[pp][1], acc[pp][2], acc[pp][3]);
        *(float4*)&g_tq[rb + 4] = make_float4(acc[pp][4], acc[pp][5], acc[pp][6], acc[pp][7]);
    }
}

// ---------------- K: per-point attention -> weighted difference vectors ----------------
#define WPB 8
__global__ void k_attn() {
    __shared__ float nb[WPB][KNN][65];
    __shared__ float tqs[WPB][64];
    __shared__ float ps[WPB][KNN];
    __shared__ int   nbi[WPB][KNN];

    int w = threadIdx.x >> 5;
    int lane = threadIdx.x & 31;
    int p = blockIdx.x * WPB + w;
    int b = p >> 12;

    if (lane < KNN) nbi[w][lane] = g_idx[p * KNN + lane];
    float q0 = g_pts[(size_t)p*64 + lane];
    float q1 = g_pts[(size_t)p*64 + 32 + lane];
    __syncwarp();
    #pragma unroll 4
    for (int k = 0; k < KNN; k++) {
        int j = nbi[w][k];
        const float* src = g_pts + ((size_t)(b << 12) + j)*64;
        nb[w][k][lane]      = src[lane];
        nb[w][k][lane + 32] = src[lane + 32];
    }
    __syncwarp();

    for (int h = 0; h < HH; h++) {
        tqs[w][lane]      = g_tq[(size_t)p*256 + h*64 + lane];
        tqs[w][lane + 32] = g_tq[(size_t)p*256 + h*64 + 32 + lane];
        __syncwarp();

        float s = -3.402823466e38f;
        if (lane < KNN) {
            float acc = 0.f;
            #pragma unroll 8
            for (int c = 0; c < 64; c++) acc += tqs[w][c] * nb[w][lane][c];
            s = acc * 0.125f;
        }
        float mx = s;
        #pragma unroll
        for (int off = 16; off; off >>= 1) mx = fmaxf(mx, __shfl_xor_sync(0xFFFFFFFFu, mx, off));
        float e = (lane < KNN) ? expf(s - mx) : 0.f;
        float sum = e;
        #pragma unroll
        for (int off = 16; off; off >>= 1) sum += __shfl_xor_sync(0xFFFFFFFFu, sum, off);
        if (lane < KNN) ps[w][lane] = e / sum;
        __syncwarp();

        float w0 = 0.f, w1 = 0.f;
        #pragma unroll 4
        for (int k = 0; k < KNN; k++) {
            float pk = ps[w][k];
            w0 += pk * (nb[w][k][lane]      - q0);
            w1 += pk * (nb[w][k][lane + 32] - q1);
        }
        g_wd[((size_t)p*HH + h)*64 + lane]      = w0;
        g_wd[((size_t)p*HH + h)*64 + 32 + lane] = w1;
        __syncwarp();
    }
}

// ---------------- K: y = Wf (128x256) @ wd^T ----------------
__global__ void k_ygemm() {
    __shared__ float Wfs[32][129];
    __shared__ float wds[64][33];
    int tid = threadIdx.y * 16 + threadIdx.x;
    int p0 = blockIdx.x * 64;
    float acc[8][4] = {};

    for (int kt = 0; kt < 8; kt++) {
        for (int t = tid; t < 4096; t += 256) {
            int o = t >> 5, k = t & 31;
            Wfs[k][o] = g_Wf[o*256 + kt*32 + k];
        }
        for (int t = tid; t < 2048; t += 256) {
            int pp = t >> 5, k = t & 31;
            wds[pp][k] = g_wd[(size_t)(p0 + pp)*256 + kt*32 + k];
        }
        __syncthreads();
        #pragma unroll 8
        for (int k = 0; k < 32; k++) {
            float a[8], bb[4];
            #pragma unroll
            for (int ii = 0; ii < 8; ii++) a[ii] = Wfs[k][threadIdx.y*8 + ii];
            #pragma unroll
            for (int jj = 0; jj < 4; jj++) bb[jj] = wds[threadIdx.x*4 + jj][k];
            #pragma unroll
            for (int ii = 0; ii < 8; ii++)
                #pragma unroll
                for (int jj = 0; jj < 4; jj++)
                    acc[ii][jj] += a[ii] * bb[jj];
        }
        __syncthreads();
    }
    #pragma unroll
    for (int ii = 0; ii < 8; ii++) {
        int o = threadIdx.y*8 + ii;
        #pragma unroll
        for (int jj = 0; jj < 4; jj++) {
            int p = p0 + threadIdx.x*4 + jj;
            g_y[((size_t)(p >> 12)*OO + o)*NN + (p & 4095)] = acc[ii][jj];
        }
    }
}

// ---------------- K: BN stats (double accumulation) ----------------
__global__ void k_bnstats() {
    __shared__ double rs[256], rss[256];
    int o = blockIdx.x;
    int tid = threadIdx.x;
    double s = 0.0, ss = 0.0;
    for (int b = 0; b < BB; b++) {
        const float* row = g_y + ((size_t)b*OO + o)*NN;
        for (int t = tid; t < NN; t += 256) {
            double v = (double)row[t];
            s += v; ss += v*v;
        }
    }
    rs[tid] = s; rss[tid] = ss;
    __syncthreads();
    for (int st = 128; st; st >>= 1) {
        if (tid < st) { rs[tid] += rs[tid + st]; rss[tid] += rss[tid + st]; }
        __syncthreads();
    }
    if (tid == 0) {
        double n = (double)(BB*NN);
        double mean = rs[0] / n;
        double var = rss[0] / n - mean*mean;
        g_mean[o] = (float)mean;
        g_istd[o] = (float)(1.0 / sqrt(var + 1e-5));
    }
}

// ---------------- K: BN apply + LeakyReLU -> out channels [0,128) ----------------
__global__ void k_bnapply(const float* __restrict__ gamma, const float* __restrict__ beta,
                          float* __restrict__ out) {
    size_t i = (size_t)blockIdx.x * blockDim.x + threadIdx.x;
    if (i >= (size_t)BB*OO*NN) return;
    int n = (int)(i & (NN-1));
    size_t t = i >> 12;
    int o = (int)(t & (OO-1));
    int b = (int)(t >> 7);
    float v = (g_y[i] - g_mean[o]) * g_istd[o] * gamma[o] + beta[o];
    v = (v >= 0.f) ? v : 0.2f * v;
    out[((size_t)b*192 + o)*NN + n] = v;
}

// ---------------- launch ----------------
extern "C" void kernel_launch(void* const* d_in, const int* in_sizes, int n_in,
                              void* d_out, int out_size) {
    const float* x     = (const float*)d_in[0];
    const float* Wq    = (const float*)d_in[1];
    const float* Wk    = (const float*)d_in[2];
    const float* Wv    = (const float*)d_in[3];
    const float* Wout  = (const float*)d_in[4];
    const float* gamma = (const float*)d_in[5];
    const float* beta  = (const float*)d_in[6];
    float* out = (float*)d_out;

    cudaFuncSetAttribute(k_pdist, cudaFuncAttributeMaxDynamicSharedMemorySize, PD_SMEM_BYTES);

    k_transpose<<<dim3(NN/32, CC/32, BB), dim3(32, 8)>>>(x);
    k_precWf<<<128, 256>>>(Wout, Wv);
    k_pdist<<<dim3(32, 32, BB), 256, PD_SMEM_BYTES>>>(x);
    k_topk3<<<PP, 128>>>();                                  // 4th launch -> profiled
    k_precM<<<64, 256>>>(Wq, Wk);
    k_copyx<<<(BB*CC*NN)/256, 256>>>(x, out);
    k_qt<<<dim3(PP/64, 2), dim3(16, 16)>>>();
    k_attn<<<PP/WPB, 256>>>();
    k_ygemm<<<PP/64, dim3(16, 16)>>>();
    k_bnstats<<<OO, 256>>>();
    k_bnapply<<<(BB*OO*NN)/256, 256>>>(gamma, beta, out);
}